// round 13
// baseline (speedup 1.0000x reference)
#include <cuda_runtime.h>
#include <cuda_bf16.h>

// ManifoldConstrainedHyperConnection — R12 phase order (same-iteration F,
// hoisted F-loads, float4 slices, G=4, L2 prefetch) with DEDICATED router
// warps: 576 threads = 16 uniform worker warps + 2 router warps. No worker
// ever blocks at the partials barrier or runs the serial sinkhorn.
//
// Per iteration (slot s = it&1):
//   workers (w0-15): A(g) -> B(g)->sP[s] -> arrive FULL(s) -> prefetch(g+1)
//                    -> hoist F-loads -> sync DONE(s) -> F(g) mix+store
//   routers (w16-17): sync FULL(s) -> reduce sP[s]->sRaw[s] -> bar5(64)
//                    -> scalar softmax+sinkhorn -> sM[s] -> arrive DONE(s)
// 2-slot ring; reuse ordered by the FULL/DONE chain.

#define WRK 24
#define DDIM 2048
#define WS 4
#define THREADS 576
#define WWARPS 16
#define G 4
#define EPSV 1e-6f

#define SP_STRIDE 100
#define SP_SLOT (WWARPS * SP_STRIDE)        // 1600 floats/slot
#define SMEM_WR (WRK * DDIM)                // 49152 floats (192 KB)
#define OFF_SP   SMEM_WR
#define OFF_RAW  (OFF_SP + 2 * SP_SLOT)     // 2 x 96
#define OFF_M    (OFF_RAW + 2 * 96)         // 2 x 64
#define SMEM_FLOATS (OFF_M + 2 * 64)
#define SMEM_BYTES (SMEM_FLOATS * 4)

#define FULLM 0xffffffffu

// named barriers: FULL_s = 1+s, DONE_s = 3+s (count 576); router-internal 5 (64)
#define BAR_ARRIVE(id)   asm volatile("bar.arrive %0, %1;" :: "r"(id), "r"(THREADS) : "memory")
#define BAR_SYNC_CTA(id) asm volatile("bar.sync %0, %1;"   :: "r"(id), "r"(THREADS) : "memory")
#define BAR_SYNC_R()     asm volatile("bar.sync 5, 64;" ::: "memory")

__device__ __forceinline__ float4 ld_cg4(const float* p) {
    return __ldcg(reinterpret_cast<const float4*>(p));
}

// butterfly step: values r[0..n-1] -> r[0..n/2-1]
#define BFLY_STEP(r, n, o)                                              \
    {                                                                   \
        const bool hi_ = (lane & (o)) != 0;                             \
        _Pragma("unroll")                                               \
        for (int v_ = 0; v_ < (n) / 2; v_++) {                          \
            float mine_  = hi_ ? r[v_ + (n) / 2] : r[v_];               \
            float other_ = hi_ ? r[v_] : r[v_ + (n) / 2];               \
            r[v_] = mine_ + __shfl_xor_sync(FULLM, other_, (o));        \
        }                                                               \
    }

__global__ void __launch_bounds__(THREADS, 1)
mchc_kernel(const float* __restrict__ x, const float* __restrict__ Wr,
            const float* __restrict__ br, float* __restrict__ out, int ntok)
{
    extern __shared__ float sm[];
    float* sWr = sm;

    const int tid  = threadIdx.x;
    const int lane = tid & 31;
    const int warp = tid >> 5;

    // stage W_router into smem once (all 18 warps help)
    for (int i = tid * 4; i < SMEM_WR; i += THREADS * 4)
        *reinterpret_cast<float4*>(sWr + i) = *reinterpret_cast<const float4*>(Wr + i);
    __syncthreads();

    const int ngroups = (ntok + G - 1) / G;
    const int gstride = gridDim.x;

    if (warp < WWARPS) {
        // ================= WORKER PATH (512 threads, uniform) =================
        const int d0 = tid * 4;
        int it = 0;

        for (int g = blockIdx.x; g < ngroups; g += gstride, it++) {
            const int s  = it & 1;
            const int n0 = g * G;
            float* sP = sm + OFF_SP + s * SP_SLOT;
            const float* sM = sm + OFF_M + s * 64;

            // ---- A: pass-1 read (L2-warm from prefetch) -> stream means ----
            float4 mx[G];
            #pragma unroll
            for (int t = 0; t < G; t++) {
                mx[t] = make_float4(0.f, 0.f, 0.f, 0.f);
                if (n0 + t < ntok) {
                    const float* p = x + (size_t)(n0 + t) * (WS * DDIM) + d0;
                    #pragma unroll
                    for (int w = 0; w < WS; w++) {
                        float4 v = ld_cg4(p + w * DDIM);
                        mx[t].x += v.x; mx[t].y += v.y; mx[t].z += v.z; mx[t].w += v.w;
                    }
                    mx[t].x *= 0.25f; mx[t].y *= 0.25f;
                    mx[t].z *= 0.25f; mx[t].w *= 0.25f;
                }
            }

            // ---- B: router partials, 3 sets of 32 values (v = 4k + t) ----
            float res0, res1, res2;
            #pragma unroll
            for (int set = 0; set < 3; set++) {
                float a[32];
                #pragma unroll
                for (int kk = 0; kk < 8; kk++) {
                    const int k = 8 * set + kk;
                    float4 wv = *reinterpret_cast<const float4*>(sWr + k * DDIM + d0);
                    #pragma unroll
                    for (int t = 0; t < G; t++)
                        a[kk * 4 + t] = wv.x * mx[t].x + wv.y * mx[t].y +
                                        wv.z * mx[t].z + wv.w * mx[t].w;
                }
                BFLY_STEP(a, 32, 16)
                BFLY_STEP(a, 16, 8)
                BFLY_STEP(a, 8, 4)
                BFLY_STEP(a, 4, 2)
                BFLY_STEP(a, 2, 1)
                if (set == 0) res0 = a[0];
                else if (set == 1) res1 = a[0];
                else res2 = a[0];
            }
            sP[warp * SP_STRIDE + lane]      = res0;
            sP[warp * SP_STRIDE + 32 + lane] = res1;
            sP[warp * SP_STRIDE + 64 + lane] = res2;
            BAR_ARRIVE(1 + s);                      // publish sP[s], non-blocking

            // ---- warm next group's x into L2 ----
            const int gn = g + gstride;
            if (gn < ngroups) {
                const char* pb = reinterpret_cast<const char*>(
                                     x + (size_t)gn * G * (WS * DDIM)) + (tid & 511) * 256;
                asm volatile("prefetch.global.L2 [%0];" :: "l"(pb));
                asm volatile("prefetch.global.L2 [%0];" :: "l"(pb + 128));
            }

            // ---- hoist F-phase loads (independent of M; L2 hits) ----
            float4 xf[G][WS];
            #pragma unroll
            for (int t = 0; t < G; t++) {
                const float* p = x + (size_t)(n0 + t) * (WS * DDIM) + d0;
                const bool ok = (n0 + t) < ntok;
                #pragma unroll
                for (int w = 0; w < WS; w++)
                    xf[t][w] = ok ? ld_cg4(p + w * DDIM) : make_float4(0,0,0,0);
            }

            BAR_SYNC_CTA(3 + s);                    // wait for M (mostly hidden)

            // ---- F: mix + store ----
            #pragma unroll
            for (int t = 0; t < G; t++) {
                if (n0 + t < ntok) {
                    float* o = out + (size_t)(n0 + t) * (WS * DDIM) + d0;
                    #pragma unroll
                    for (int i = 0; i < WS; i++) {
                        float4 Mi = *reinterpret_cast<const float4*>(sM + t * 16 + i * 4);
                        float4 ov;
                        ov.x = Mi.x*xf[t][0].x + Mi.y*xf[t][1].x + Mi.z*xf[t][2].x + Mi.w*xf[t][3].x;
                        ov.y = Mi.x*xf[t][0].y + Mi.y*xf[t][1].y + Mi.z*xf[t][2].y + Mi.w*xf[t][3].y;
                        ov.z = Mi.x*xf[t][0].z + Mi.y*xf[t][1].z + Mi.z*xf[t][2].z + Mi.w*xf[t][3].z;
                        ov.w = Mi.x*xf[t][0].w + Mi.y*xf[t][1].w + Mi.z*xf[t][2].w + Mi.w*xf[t][3].w;
                        __stcs(reinterpret_cast<float4*>(o + i * DDIM), ov);
                    }
                }
            }
        }
    } else {
        // ================= ROUTER PATH (warps 16-17, 64 threads) =================
        const int rwarp = warp - WWARPS;              // 0 or 1
        const int rv    = rwarp * 32 + lane;          // value id 0..63
        int it = 0;

        for (int g = blockIdx.x; g < ngroups; g += gstride, it++) {
            const int s = it & 1;
            float* sP   = sm + OFF_SP + s * SP_SLOT;
            float* sRaw = sm + OFF_RAW + s * 96;
            float* sM   = sm + OFF_M + s * 64;

            BAR_SYNC_CTA(1 + s);                      // FULL_s: sP complete

            // reduce 96 values over 16 worker warps; value v = 4k + t
            {
                float acc = __ldg(br + (rv >> 2));
                #pragma unroll
                for (int w = 0; w < WWARPS; w++)
                    acc += sP[w * SP_STRIDE + rv];
                sRaw[rv] = acc;
                if (rv < 32) {
                    const int v2 = 64 + rv;
                    float acc2 = __ldg(br + (v2 >> 2));
                    #pragma unroll
                    for (int w = 0; w < WWARPS; w++)
                        acc2 += sP[w * SP_STRIDE + v2];
                    sRaw[v2] = acc2;
                }
            }
            BAR_SYNC_R();                             // both router warps see sRaw

            // scalar softmax + sinkhorn; token t = 2*rwarp + (lane>>4)
            {
                const int t = 2 * rwarp + (lane >> 4);

                float p0 = sRaw[0*4+t], p1 = sRaw[1*4+t], p2 = sRaw[2*4+t], p3 = sRaw[3*4+t];
                float mp = fmaxf(fmaxf(p0, p1), fmaxf(p2, p3));
                p0 = __expf(p0 - mp); p1 = __expf(p1 - mp);
                p2 = __expf(p2 - mp); p3 = __expf(p3 - mp);
                float isp = __fdividef(1.f, p0 + p1 + p2 + p3);
                p0 *= isp; p1 *= isp; p2 *= isp; p3 *= isp;

                float q0 = sRaw[4*4+t], q1 = sRaw[5*4+t], q2 = sRaw[6*4+t], q3 = sRaw[7*4+t];
                float mq = fmaxf(fmaxf(q0, q1), fmaxf(q2, q3));
                q0 = __expf(q0 - mq); q1 = __expf(q1 - mq);
                q2 = __expf(q2 - mq); q3 = __expf(q3 - mq);
                float isq = __fdividef(1.f, q0 + q1 + q2 + q3);
                q0 *= isq; q1 *= isq; q2 *= isq; q3 *= isq;

                float av[16];
                #pragma unroll
                for (int i = 0; i < 4; i++)
                    #pragma unroll
                    for (int j = 0; j < 4; j++)
                        av[i*4+j] = __expf(sRaw[(8 + i*4 + j)*4 + t] + (i == j ? 2.0f : -2.0f));

                #pragma unroll
                for (int itn = 0; itn < 4; itn++) {
                    #pragma unroll
                    for (int i = 0; i < 4; i++) {
                        float rs  = av[i*4] + av[i*4+1] + av[i*4+2] + av[i*4+3];
                        float inv = __fdividef(1.f, fmaxf(rs, EPSV));
                        av[i*4] *= inv; av[i*4+1] *= inv; av[i*4+2] *= inv; av[i*4+3] *= inv;
                    }
                    #pragma unroll
                    for (int j = 0; j < 4; j++) {
                        float cs  = av[j] + av[4+j] + av[8+j] + av[12+j];
                        float inv = __fdividef(1.f, fmaxf(cs, EPSV));
                        av[j] *= inv; av[4+j] *= inv; av[8+j] *= inv; av[12+j] *= inv;
                    }
                }

                if ((lane & 15) == 0) {
                    const float pre[4]  = {p0, p1, p2, p3};
                    const float post[4] = {q0, q1, q2, q3};
                    #pragma unroll
                    for (int i = 0; i < 4; i++) {
                        float4 mrow;
                        mrow.x = av[i*4+0] + post[i] * pre[0];
                        mrow.y = av[i*4+1] + post[i] * pre[1];
                        mrow.z = av[i*4+2] + post[i] * pre[2];
                        mrow.w = av[i*4+3] + post[i] * pre[3];
                        *reinterpret_cast<float4*>(sM + t * 16 + i * 4) = mrow;
                    }
                }
            }
            BAR_ARRIVE(3 + s);                        // publish sM[s] (DONE)
        }
    }
}

extern "C" void kernel_launch(void* const* d_in, const int* in_sizes, int n_in,
                              void* d_out, int out_size)
{
    const float* x  = (const float*)d_in[0];
    const float* Wr = (const float*)d_in[1];
    const float* br = (const float*)d_in[2];
    float* out = (float*)d_out;

    int ntok = in_sizes[0] / (WS * DDIM);   // 8192

    cudaFuncSetAttribute(mchc_kernel,
                         cudaFuncAttributeMaxDynamicSharedMemorySize, SMEM_BYTES);

    int sms = 148, dev = 0;
    if (cudaGetDevice(&dev) == cudaSuccess) {
        int v = 0;
        if (cudaDeviceGetAttribute(&v, cudaDevAttrMultiProcessorCount, dev) == cudaSuccess && v > 0)
            sms = v;
    }
    int ngroups = (ntok + G - 1) / G;
    int grid = (ngroups < sms) ? ngroups : sms;

    mchc_kernel<<<grid, THREADS, SMEM_BYTES>>>(x, Wr, br, out, ntok);
}

// round 14
// speedup vs baseline: 1.4453x; 1.4453x over previous
#include <cuda_runtime.h>
#include <cuda_bf16.h>

// ManifoldConstrainedHyperConnection — R12 envelope (512 thr, float4 slices,
// G=4, same-iteration F, hoisted F-loads, L2 prefetch, single-slot smem),
// with a slimmer router path:
//   - warps 2-15: pure workers (arrive barA, prefetch, hoist xf, sync barB, F)
//   - warps 0-1:  write sP, hoist xf (flies during barA wait), sync barA,
//                 each reduces ONLY its own 2 tokens' 48 values (no bar3),
//                 scalar sinkhorn, write own sM share, sync barB (releases
//                 workers + drains STS; no bar4), prefetch, F with hoisted xf.
// barA: id1 count512 (448 arrive + 64 sync). barB: id2 count512 (all sync).

#define WRK 24
#define DDIM 2048
#define WS 4
#define THREADS 512
#define NW 16
#define G 4
#define EPSV 1e-6f

#define SMEM_WR (WRK * DDIM)            // 49152 floats (192 KB)
#define SP_STRIDE 100
#define SMEM_SP (NW * SP_STRIDE)        // 1600 floats
#define SMEM_FLOATS (SMEM_WR + SMEM_SP + 96 + 64)
#define SMEM_BYTES (SMEM_FLOATS * 4)

#define FULLM 0xffffffffu

#define BAR_ARRIVE(id, n)  asm volatile("bar.arrive %0, %1;" :: "r"(id), "r"(n) : "memory")
#define BAR_SYNC(id, n)    asm volatile("bar.sync %0, %1;"   :: "r"(id), "r"(n) : "memory")

__device__ __forceinline__ float4 ld_cg4(const float* p) {
    return __ldcg(reinterpret_cast<const float4*>(p));
}

// butterfly step: values r[0..n-1] -> r[0..n/2-1]
#define BFLY_STEP(r, n, o)                                              \
    {                                                                   \
        const bool hi_ = (lane & (o)) != 0;                             \
        _Pragma("unroll")                                               \
        for (int v_ = 0; v_ < (n) / 2; v_++) {                          \
            float mine_  = hi_ ? r[v_ + (n) / 2] : r[v_];               \
            float other_ = hi_ ? r[v_] : r[v_ + (n) / 2];               \
            r[v_] = mine_ + __shfl_xor_sync(FULLM, other_, (o));        \
        }                                                               \
    }

__global__ void __launch_bounds__(THREADS, 1)
mchc_kernel(const float* __restrict__ x, const float* __restrict__ Wr,
            const float* __restrict__ br, float* __restrict__ out, int ntok)
{
    extern __shared__ float sm[];
    float* sWr  = sm;
    float* sP   = sm + SMEM_WR;
    float* sRaw = sP + SMEM_SP;      // 96 floats, raw index v = 4k + t
    float* sM   = sRaw + 96;         // 64 floats: sM[t*16 + i*4 + j]

    const int tid  = threadIdx.x;
    const int lane = tid & 31;
    const int warp = tid >> 5;
    const int d0   = tid * 4;

    // stage W_router into smem once
    for (int i = tid * 4; i < SMEM_WR; i += THREADS * 4)
        *reinterpret_cast<float4*>(sWr + i) = *reinterpret_cast<const float4*>(Wr + i);
    __syncthreads();

    const int ngroups = (ntok + G - 1) / G;

    for (int g = blockIdx.x; g < ngroups; g += gridDim.x) {
        const int n0 = g * G;

        // ---- A: pass-1 read (L2-warm from prefetch) -> stream means ----
        float4 mx[G];
        #pragma unroll
        for (int t = 0; t < G; t++) {
            mx[t] = make_float4(0.f, 0.f, 0.f, 0.f);
            if (n0 + t < ntok) {
                const float* p = x + (size_t)(n0 + t) * (WS * DDIM) + d0;
                #pragma unroll
                for (int w = 0; w < WS; w++) {
                    float4 v = ld_cg4(p + w * DDIM);
                    mx[t].x += v.x; mx[t].y += v.y; mx[t].z += v.z; mx[t].w += v.w;
                }
                mx[t].x *= 0.25f; mx[t].y *= 0.25f; mx[t].z *= 0.25f; mx[t].w *= 0.25f;
            }
        }

        // ---- B: router partials, 3 sets of 32 values (v = 4k + t) ----
        float res0, res1, res2;
        #pragma unroll
        for (int set = 0; set < 3; set++) {
            float a[32];
            #pragma unroll
            for (int kk = 0; kk < 8; kk++) {
                const int k = 8 * set + kk;
                float4 wv = *reinterpret_cast<const float4*>(sWr + k * DDIM + d0);
                #pragma unroll
                for (int t = 0; t < G; t++)
                    a[kk * 4 + t] = wv.x * mx[t].x + wv.y * mx[t].y +
                                    wv.z * mx[t].z + wv.w * mx[t].w;
            }
            BFLY_STEP(a, 32, 16)
            BFLY_STEP(a, 16, 8)
            BFLY_STEP(a, 8, 4)
            BFLY_STEP(a, 4, 2)
            BFLY_STEP(a, 2, 1)
            if (set == 0) res0 = a[0];
            else if (set == 1) res1 = a[0];
            else res2 = a[0];
        }
        sP[warp * SP_STRIDE + lane]      = res0;
        sP[warp * SP_STRIDE + 32 + lane] = res1;
        sP[warp * SP_STRIDE + 64 + lane] = res2;

        if (warp >= 2) {
            // ============ WORKER (warps 2-15) ============
            BAR_ARRIVE(1, THREADS);                 // publish sP, non-blocking

            // warm next group's x into L2
            const int gn = g + gridDim.x;
            if (gn < ngroups) {
                const char* pb = reinterpret_cast<const char*>(
                                     x + (size_t)gn * G * (WS * DDIM)) + tid * 256;
                asm volatile("prefetch.global.L2 [%0];" :: "l"(pb));
                asm volatile("prefetch.global.L2 [%0];" :: "l"(pb + 128));
            }

            // hoist F-phase loads (independent of M; L2 hits)
            float4 xf[G][WS];
            #pragma unroll
            for (int t = 0; t < G; t++) {
                const float* p = x + (size_t)(n0 + t) * (WS * DDIM) + d0;
                const bool ok = (n0 + t) < ntok;
                #pragma unroll
                for (int w = 0; w < WS; w++)
                    xf[t][w] = ok ? ld_cg4(p + w * DDIM) : make_float4(0,0,0,0);
            }

            BAR_SYNC(2, THREADS);                   // wait for M (hidden by loads)

            #pragma unroll
            for (int t = 0; t < G; t++) {
                if (n0 + t < ntok) {
                    float* o = out + (size_t)(n0 + t) * (WS * DDIM) + d0;
                    #pragma unroll
                    for (int i = 0; i < WS; i++) {
                        float4 Mi = *reinterpret_cast<const float4*>(sM + t * 16 + i * 4);
                        float4 ov;
                        ov.x = Mi.x*xf[t][0].x + Mi.y*xf[t][1].x + Mi.z*xf[t][2].x + Mi.w*xf[t][3].x;
                        ov.y = Mi.x*xf[t][0].y + Mi.y*xf[t][1].y + Mi.z*xf[t][2].y + Mi.w*xf[t][3].y;
                        ov.z = Mi.x*xf[t][0].z + Mi.y*xf[t][1].z + Mi.z*xf[t][2].z + Mi.w*xf[t][3].z;
                        ov.w = Mi.x*xf[t][0].w + Mi.y*xf[t][1].w + Mi.z*xf[t][2].w + Mi.w*xf[t][3].w;
                        __stcs(reinterpret_cast<float4*>(o + i * DDIM), ov);
                    }
                }
            }
        } else {
            // ============ ROUTER (warps 0-1; also full workers) ============
            // hoist F-loads BEFORE barA: they fly during the barrier wait
            float4 xf[G][WS];
            #pragma unroll
            for (int t = 0; t < G; t++) {
                const float* p = x + (size_t)(n0 + t) * (WS * DDIM) + d0;
                const bool ok = (n0 + t) < ntok;
                #pragma unroll
                for (int w = 0; w < WS; w++)
                    xf[t][w] = ok ? ld_cg4(p + w * DDIM) : make_float4(0,0,0,0);
            }

            BAR_SYNC(1, THREADS);                   // barA: sP complete

            // reduce ONLY this warp's 2 tokens' values (t parity = lane&1)
            // pass 1: k = lane>>1 (0..15), t = 2*warp + (lane&1)
            {
                const int k = lane >> 1;
                const int t = 2 * warp + (lane & 1);
                const int v = 4 * k + t;
                float acc = __ldg(br + k);
                #pragma unroll
                for (int w = 0; w < NW; w++)
                    acc += sP[w * SP_STRIDE + v];
                sRaw[v] = acc;
            }
            // pass 2: k = 16 + (lane>>1) for lane < 16
            if (lane < 16) {
                const int k = 16 + (lane >> 1);
                const int t = 2 * warp + (lane & 1);
                const int v = 4 * k + t;
                float acc = __ldg(br + k);
                #pragma unroll
                for (int w = 0; w < NW; w++)
                    acc += sP[w * SP_STRIDE + v];
                sRaw[v] = acc;
            }
            __syncwarp();                           // sRaw visible within warp

            // scalar softmax + sinkhorn; token t = 2*warp + (lane>>4)
            {
                const int t = 2 * warp + (lane >> 4);

                float p0 = sRaw[0*4+t], p1 = sRaw[1*4+t], p2 = sRaw[2*4+t], p3 = sRaw[3*4+t];
                float mp = fmaxf(fmaxf(p0, p1), fmaxf(p2, p3));
                p0 = __expf(p0 - mp); p1 = __expf(p1 - mp);
                p2 = __expf(p2 - mp); p3 = __expf(p3 - mp);
                float isp = __fdividef(1.f, p0 + p1 + p2 + p3);
                p0 *= isp; p1 *= isp; p2 *= isp; p3 *= isp;

                float q0 = sRaw[4*4+t], q1 = sRaw[5*4+t], q2 = sRaw[6*4+t], q3 = sRaw[7*4+t];
                float mq = fmaxf(fmaxf(q0, q1), fmaxf(q2, q3));
                q0 = __expf(q0 - mq); q1 = __expf(q1 - mq);
                q2 = __expf(q2 - mq); q3 = __expf(q3 - mq);
                float isq = __fdividef(1.f, q0 + q1 + q2 + q3);
                q0 *= isq; q1 *= isq; q2 *= isq; q3 *= isq;

                float av[16];
                #pragma unroll
                for (int i = 0; i < 4; i++)
                    #pragma unroll
                    for (int j = 0; j < 4; j++)
                        av[i*4+j] = __expf(sRaw[(8 + i*4 + j)*4 + t] + (i == j ? 2.0f : -2.0f));

                #pragma unroll
                for (int itn = 0; itn < 4; itn++) {
                    #pragma unroll
                    for (int i = 0; i < 4; i++) {
                        float rs  = av[i*4] + av[i*4+1] + av[i*4+2] + av[i*4+3];
                        float inv = __fdividef(1.f, fmaxf(rs, EPSV));
                        av[i*4] *= inv; av[i*4+1] *= inv; av[i*4+2] *= inv; av[i*4+3] *= inv;
                    }
                    #pragma unroll
                    for (int j = 0; j < 4; j++) {
                        float cs  = av[j] + av[4+j] + av[8+j] + av[12+j];
                        float inv = __fdividef(1.f, fmaxf(cs, EPSV));
                        av[j] *= inv; av[4+j] *= inv; av[8+j] *= inv; av[12+j] *= inv;
                    }
                }

                if ((lane & 15) == 0) {
                    const float pre[4]  = {p0, p1, p2, p3};
                    const float post[4] = {q0, q1, q2, q3};
                    #pragma unroll
                    for (int i = 0; i < 4; i++) {
                        float4 mrow;
                        mrow.x = av[i*4+0] + post[i] * pre[0];
                        mrow.y = av[i*4+1] + post[i] * pre[1];
                        mrow.z = av[i*4+2] + post[i] * pre[2];
                        mrow.w = av[i*4+3] + post[i] * pre[3];
                        *reinterpret_cast<float4*>(sM + t * 16 + i * 4) = mrow;
                    }
                }
            }
            BAR_SYNC(2, THREADS);                   // barB: releases workers,
                                                    // drains sM stores (both warps)

            // prefetch share
            const int gn = g + gridDim.x;
            if (gn < ngroups) {
                const char* pb = reinterpret_cast<const char*>(
                                     x + (size_t)gn * G * (WS * DDIM)) + tid * 256;
                asm volatile("prefetch.global.L2 [%0];" :: "l"(pb));
                asm volatile("prefetch.global.L2 [%0];" :: "l"(pb + 128));
            }

            // F with hoisted xf (full M now visible)
            #pragma unroll
            for (int t = 0; t < G; t++) {
                if (n0 + t < ntok) {
                    float* o = out + (size_t)(n0 + t) * (WS * DDIM) + d0;
                    #pragma unroll
                    for (int i = 0; i < WS; i++) {
                        float4 Mi = *reinterpret_cast<const float4*>(sM + t * 16 + i * 4);
                        float4 ov;
                        ov.x = Mi.x*xf[t][0].x + Mi.y*xf[t][1].x + Mi.z*xf[t][2].x + Mi.w*xf[t][3].x;
                        ov.y = Mi.x*xf[t][0].y + Mi.y*xf[t][1].y + Mi.z*xf[t][2].y + Mi.w*xf[t][3].y;
                        ov.z = Mi.x*xf[t][0].z + Mi.y*xf[t][1].z + Mi.z*xf[t][2].z + Mi.w*xf[t][3].z;
                        ov.w = Mi.x*xf[t][0].w + Mi.y*xf[t][1].w + Mi.z*xf[t][2].w + Mi.w*xf[t][3].w;
                        __stcs(reinterpret_cast<float4*>(o + i * DDIM), ov);
                    }
                }
            }
        }
        // single-slot reuse ordering:
        //   sP(it+1): written after barB(it) sync (program order)  ✓
        //   sM(it+1): routers write only after barA(it+1), which requires all
        //             workers arrived, i.e. finished F(it) reads of sM       ✓
        //   sRaw(it+1): router-private between barA and barB                 ✓
    }
}

extern "C" void kernel_launch(void* const* d_in, const int* in_sizes, int n_in,
                              void* d_out, int out_size)
{
    const float* x  = (const float*)d_in[0];
    const float* Wr = (const float*)d_in[1];
    const float* br = (const float*)d_in[2];
    float* out = (float*)d_out;

    int ntok = in_sizes[0] / (WS * DDIM);   // 8192

    cudaFuncSetAttribute(mchc_kernel,
                         cudaFuncAttributeMaxDynamicSharedMemorySize, SMEM_BYTES);

    int sms = 148, dev = 0;
    if (cudaGetDevice(&dev) == cudaSuccess) {
        int v = 0;
        if (cudaDeviceGetAttribute(&v, cudaDevAttrMultiProcessorCount, dev) == cudaSuccess && v > 0)
            sms = v;
    }
    int ngroups = (ntok + G - 1) / G;
    int grid = (ngroups < sms) ? ngroups : sms;

    mchc_kernel<<<grid, THREADS, SMEM_BYTES>>>(x, Wr, br, out, ntok);
}